// round 13
// baseline (speedup 1.0000x reference)
#include <cuda_runtime.h>
#include <math.h>

#define B_   4
#define CIN  1024
#define CB   256
#define H_   64
#define W_   64
#define HW   (H_*W_)
#define KOFF 9
#define CQ   8                        // conv channel-split ways
#define DSPLIT 4                      // deform channel-split ways

// ---------------- scratch (device globals; no runtime allocation) ----------
__device__ float g_out1[(size_t)B_*CB*HW];              // 16.7 MB
__device__ float g_omp [(size_t)CQ*B_*27*HW];           // conv partial sums
__device__ float g_samp[(size_t)B_*CB*KOFF*HW];         // 151 MB
__device__ float g_out2[(size_t)B_*CB*HW];              // 16.7 MB
__device__ float g_out3[(size_t)B_*CIN*HW];             // 67 MB (GEMM3 out)
__device__ float g_ap1[(size_t)CIN*CB];                 // w1 perm
__device__ float g_ap2[(size_t)CB*KOFF*CB];             // w2 perm
__device__ float g_ap3[(size_t)CB*CIN];                 // w3 perm
__device__ float g_gnp[(size_t)B_*32*32*2];             // GN tile partials [b][g][tile][2]
__device__ float g_gns[(size_t)B_*32*2];                // GN mean/rstd per (b,g)

__device__ __forceinline__ unsigned f2tf32(float f) {
    unsigned u;
    asm("cvt.rna.tf32.f32 %0, %1;" : "=r"(u) : "f"(f));
    return u;
}
__device__ __forceinline__ float round_tf32(float f) {
    return __uint_as_float(f2tf32(f));
}

__device__ __forceinline__ void cp_async16(void* smem_dst, const void* gsrc) {
    unsigned s = (unsigned)__cvta_generic_to_shared(smem_dst);
    asm volatile("cp.async.cg.shared.global [%0], [%1], 16;\n" :: "r"(s), "l"(gsrc));
}
__device__ __forceinline__ void cp_commit() {
    asm volatile("cp.async.commit_group;\n");
}
template <int N>
__device__ __forceinline__ void cp_wait() {
    asm volatile("cp.async.wait_group %0;\n" :: "n"(N));
}

// ---------------- batched TF32 tensor-core GEMM: C[b] = Aperm @ B[b] -------
// gmode: 0 = no stats, 1 = GroupNorm stats for 8-row groups (M=256 GEMMs),
//        2 = GroupNorm stats for 32-row groups (M=1024 GEMM3).
#define GSTAGE   3
#define GK       32
#define GROW     136
#define A_STG    (GK * 128)
#define B_STG    (GK * GROW)
#define GEMM_SMEM ((GSTAGE * (A_STG + B_STG)) * 4)
__global__ void __launch_bounds__(256, 2) tf32_gemm_kernel(
    const float* __restrict__ AP, const float* __restrict__ Bm,
    float* __restrict__ Cm, int M, int N, int K,
    size_t strideB, size_t strideC, float* __restrict__ gstats, int gmode)
{
    extern __shared__ float sm_[];
    float (*As)[4][8][32][4] = (float(*)[4][8][32][4])sm_;
    float (*Bs)[GK][GROW]    = (float(*)[GK][GROW])(sm_ + GSTAGE * A_STG);

    const float* Bp = Bm + (size_t)blockIdx.z * strideB;
    float*       Cp = Cm + (size_t)blockIdx.z * strideC;
    const int bm = blockIdx.y * 128;
    const int bn = blockIdx.x * 128;
    const int nmb = M >> 4;
    const int mb0 = bm >> 4;

    const int tid  = threadIdx.x;
    const int lane = tid & 31;
    const int warp = tid >> 5;
    const int wmb = (warp & 1) * 4;
    const int wn  = (warp >> 1) * 32;
    const int grp = lane >> 2;
    const int tig = lane & 3;

    float acc[4][4][4];
#pragma unroll
    for (int mi = 0; mi < 4; mi++)
#pragma unroll
        for (int ni = 0; ni < 4; ni++)
#pragma unroll
            for (int i = 0; i < 4; i++) acc[mi][ni][i] = 0.f;

    const int nstage = K / GK;

#define LOAD_STAGE(buf, ks)                                                   \
    do {                                                                      \
        _Pragma("unroll")                                                     \
        for (int j = 0; j < 4; j++) {                                         \
            const int id  = tid + 256 * j;                                    \
            const int kb2 = id >> 8;                                          \
            const int rem = id & 255;                                         \
            const int mb  = rem >> 5;                                         \
            const int ln  = rem & 31;                                         \
            cp_async16(&As[buf][kb2][mb][ln][0],                              \
                AP + (((size_t)((ks) * 4 + kb2) * nmb + mb0 + mb) * 32 + ln) * 4); \
            const int kk  = id >> 5;                                          \
            const int col = (id & 31) * 4;                                    \
            cp_async16(&Bs[buf][kk][col],                                     \
                Bp + (size_t)((ks) * GK + kk) * N + bn + col);                \
        }                                                                     \
    } while (0)

    LOAD_STAGE(0, 0); cp_commit();
    LOAD_STAGE(1, 1); cp_commit();

    int cur = 0;
    for (int ks = 0; ks < nstage; ks++) {
        cp_wait<1>();
        __syncthreads();

#pragma unroll
        for (int kb2 = 0; kb2 < 4; kb2++) {
            unsigned a[4][4], b[4][2];
#pragma unroll
            for (int mi = 0; mi < 4; mi++) {
                const float4 av = *(const float4*)&As[cur][kb2][wmb + mi][lane][0];
                a[mi][0] = __float_as_uint(av.x);
                a[mi][1] = __float_as_uint(av.y);
                a[mi][2] = __float_as_uint(av.z);
                a[mi][3] = __float_as_uint(av.w);
            }
#pragma unroll
            for (int ni = 0; ni < 4; ni++) {
                const int n = wn + ni * 8 + grp;
                b[ni][0] = __float_as_uint(Bs[cur][kb2 * 8 + tig    ][n]);
                b[ni][1] = __float_as_uint(Bs[cur][kb2 * 8 + tig + 4][n]);
            }
#pragma unroll
            for (int mi = 0; mi < 4; mi++)
#pragma unroll
                for (int ni = 0; ni < 4; ni++) {
                    asm volatile(
                        "mma.sync.aligned.m16n8k8.row.col.f32.tf32.tf32.f32 "
                        "{%0,%1,%2,%3}, {%4,%5,%6,%7}, {%8,%9}, {%0,%1,%2,%3};\n"
                        : "+f"(acc[mi][ni][0]), "+f"(acc[mi][ni][1]),
                          "+f"(acc[mi][ni][2]), "+f"(acc[mi][ni][3])
                        : "r"(a[mi][0]), "r"(a[mi][1]), "r"(a[mi][2]), "r"(a[mi][3]),
                          "r"(b[ni][0]), "r"(b[ni][1]));
                }
        }

        if (ks + 2 < nstage) {
            const int buf = cur + 2 >= GSTAGE ? cur + 2 - GSTAGE : cur + 2;
            LOAD_STAGE(buf, ks + 2);
        }
        cp_commit();
        cur = cur + 1 >= GSTAGE ? 0 : cur + 1;
    }

    // epilogue: store C
#pragma unroll
    for (int mi = 0; mi < 4; mi++) {
        const int row = bm + (warp & 1) * 64 + mi * 16 + grp;
#pragma unroll
        for (int ni = 0; ni < 4; ni++) {
            const int col = bn + wn + ni * 8 + tig * 2;
            float2 v0 = make_float2(acc[mi][ni][0], acc[mi][ni][1]);
            float2 v1 = make_float2(acc[mi][ni][2], acc[mi][ni][3]);
            *(float2*)(Cp + (size_t)row * N + col)       = v0;
            *(float2*)(Cp + (size_t)(row + 8) * N + col) = v1;
        }
    }

    if (gmode == 1) {
        // 8-row groups: 16 per tile. gl = (warp&1)*8 + mi*2 + h, h = (i>=2)
        float sg[4][2], qg[4][2];
#pragma unroll
        for (int mi = 0; mi < 4; mi++)
#pragma unroll
            for (int h = 0; h < 2; h++) {
                float s = 0.f, q = 0.f;
#pragma unroll
                for (int ni = 0; ni < 4; ni++)
#pragma unroll
                    for (int i = h * 2; i < h * 2 + 2; i++) {
                        const float v = acc[mi][ni][i];
                        s += v; q += v * v;
                    }
                sg[mi][h] = s; qg[mi][h] = q;
            }
#pragma unroll
        for (int mi = 0; mi < 4; mi++)
#pragma unroll
            for (int h = 0; h < 2; h++)
#pragma unroll
                for (int o = 16; o > 0; o >>= 1) {
                    sg[mi][h] += __shfl_down_sync(0xFFFFFFFFu, sg[mi][h], o);
                    qg[mi][h] += __shfl_down_sync(0xFFFFFFFFu, qg[mi][h], o);
                }
        __syncthreads();
        float* red = sm_;                 // [8 warps][8 j][2]
        if (lane == 0) {
#pragma unroll
            for (int mi = 0; mi < 4; mi++)
#pragma unroll
                for (int h = 0; h < 2; h++) {
                    const int j = mi * 2 + h;
                    red[(warp * 8 + j) * 2 + 0] = sg[mi][h];
                    red[(warp * 8 + j) * 2 + 1] = qg[mi][h];
                }
        }
        __syncthreads();
        if (tid < 16) {                   // tid = gl
            const int par = tid >> 3;
            const int j   = tid & 7;
            float s = 0.f, q = 0.f;
#pragma unroll
            for (int w = 0; w < 4; w++) {
                const int wi = par + w * 2;
                s += red[(wi * 8 + j) * 2 + 0];
                q += red[(wi * 8 + j) * 2 + 1];
            }
            const size_t gi = (((size_t)blockIdx.z * 32 + (bm >> 3) + tid) * (N >> 7)
                               + (bn >> 7)) * 2;
            gstats[gi]     = s;
            gstats[gi + 1] = q;
        }
    } else if (gmode == 2) {
        // 32-row groups: 4 per tile (GEMM3)
        float s0 = 0.f, q0 = 0.f, s1 = 0.f, q1 = 0.f;
#pragma unroll
        for (int mi = 0; mi < 4; mi++) {
            float s = 0.f, q = 0.f;
#pragma unroll
            for (int ni = 0; ni < 4; ni++)
#pragma unroll
                for (int i = 0; i < 4; i++) {
                    const float v = acc[mi][ni][i];
                    s += v; q += v * v;
                }
            if (mi < 2) { s0 += s; q0 += q; } else { s1 += s; q1 += q; }
        }
#pragma unroll
        for (int o = 16; o > 0; o >>= 1) {
            s0 += __shfl_down_sync(0xFFFFFFFFu, s0, o);
            q0 += __shfl_down_sync(0xFFFFFFFFu, q0, o);
            s1 += __shfl_down_sync(0xFFFFFFFFu, s1, o);
            q1 += __shfl_down_sync(0xFFFFFFFFu, q1, o);
        }
        __syncthreads();
        float* red = sm_;
        if (lane == 0) {
            red[warp * 4 + 0] = s0; red[warp * 4 + 1] = q0;
            red[warp * 4 + 2] = s1; red[warp * 4 + 3] = q1;
        }
        __syncthreads();
        if (tid < 4) {
            const int par = tid >> 1;
            const int off = (tid & 1) * 2;
            float s = 0.f, q = 0.f;
#pragma unroll
            for (int j = 0; j < 4; j++) {
                const int w = par + j * 2;
                s += red[w * 4 + off];
                q += red[w * 4 + off + 1];
            }
            const size_t gi = (((size_t)blockIdx.z * 32 + (bm >> 5) + tid) * (N >> 7)
                               + (bn >> 7)) * 2;
            gstats[gi]     = s;
            gstats[gi + 1] = q;
        }
    }
#undef LOAD_STAGE
}

// ---------------- GN stats reduce: tile partials -> mean/rstd --------------
__global__ void gn_reduce_kernel(const float* __restrict__ gnp,
                                 float* __restrict__ gns, float n_per_group)
{
    const int i = threadIdx.x;
    if (i >= B_ * 32) return;
    float s = 0.f, q = 0.f;
    const float* p = gnp + (size_t)i * 32 * 2;
#pragma unroll
    for (int t = 0; t < 32; t++) { s += p[t * 2]; q += p[t * 2 + 1]; }
    const float mean = s / n_per_group;
    const float var  = q / n_per_group - mean * mean;
    gns[i * 2]     = mean;
    gns[i * 2 + 1] = rsqrtf(var + 1e-5f);
}

// ---------------- GN apply (flat) + ReLU, in place; CPG = channels/group ---
template <int C, int CPG>
__global__ void gn_apply_relu_kernel(float* __restrict__ data,
                                     const float* __restrict__ gns,
                                     const float* __restrict__ scale,
                                     const float* __restrict__ bias)
{
    const int idx = blockIdx.x * blockDim.x + threadIdx.x;
    if (idx >= B_ * C * HW / 4) return;
    const int i4 = idx * 4;
    const int b = i4 / (C * HW);
    const int c = (i4 / HW) % C;
    const int g = b * 32 + c / CPG;
    const float mean = gns[g * 2];
    const float rstd = gns[g * 2 + 1];
    const float a = rstd * scale[c];
    const float d = bias[c] - mean * a;
    float4 v = ((const float4*)data)[idx];
    v.x = fmaxf(v.x * a + d, 0.f);
    v.y = fmaxf(v.y * a + d, 0.f);
    v.z = fmaxf(v.z * a + d, 0.f);
    v.w = fmaxf(v.w * a + d, 0.f);
    ((float4*)data)[idx] = v;
}

// ---------------- GN3 apply (flat) + residual + ReLU -> output -------------
__global__ void gn_res_apply_kernel(const float* __restrict__ in,
                                    const float* __restrict__ xres,
                                    const float* __restrict__ gns,
                                    const float* __restrict__ scale,
                                    const float* __restrict__ bias,
                                    float* __restrict__ out)
{
    const int idx = blockIdx.x * blockDim.x + threadIdx.x;
    if (idx >= B_ * CIN * HW / 4) return;
    const int i4 = idx * 4;
    const int b = i4 / (CIN * HW);
    const int c = (i4 / HW) % CIN;
    const int g = b * 32 + (c >> 5);
    const float mean = gns[g * 2];
    const float rstd = gns[g * 2 + 1];
    const float a = rstd * scale[c];
    const float d = bias[c] - mean * a;
    float4 v = ((const float4*)in)[idx];
    float4 rr = ((const float4*)xres)[idx];
    v.x = fmaxf(v.x * a + d + rr.x, 0.f);
    v.y = fmaxf(v.y * a + d + rr.y, 0.f);
    v.z = fmaxf(v.z * a + d + rr.z, 0.f);
    v.w = fmaxf(v.w * a + d + rr.w, 0.f);
    ((float4*)out)[idx] = v;
}

// ---------------- weight permute + tf32-round ------------------------------
__global__ void aperm_round_kernel(const float* __restrict__ A,
                                   float* __restrict__ AP, int M, int K)
{
    const int i = blockIdx.x * blockDim.x + threadIdx.x;
    if (i >= M * K) return;
    const int blk = i >> 7;
    const int l   = (i >> 2) & 31;
    const int v   = i & 3;
    const int nmb = M >> 4;
    const int kb = blk / nmb, mb = blk % nmb;
    const int tig = (l & 3) + ((v >> 1) << 2);
    const int grp = (l >> 2) + ((v & 1) << 3);
    const int m = mb * 16 + grp;
    const int k = kb * 8 + tig;
    AP[i] = round_tf32(A[(size_t)m * K + k]);
}

// ---------------- 3x3 offset conv (27 out ch), pad=1, channel-split 8 ------
__global__ void __launch_bounds__(256) conv_off_kernel(
    const float* __restrict__ in,
    const float* __restrict__ w,
    float* __restrict__ omp)
{
    const int bx = blockIdx.x;
    const int by = blockIdx.y;
    const int b = blockIdx.z >> 3;
    const int q = blockIdx.z & 7;
    const int tid = threadIdx.x;
    const int tx = tid & 15, ty = tid >> 4;

    __shared__ float s_in[8][18][18];
    __shared__ float s_w[8][9][28];

    float acc[28];
#pragma unroll
    for (int j = 0; j < 28; j++) acc[j] = 0.f;

    const int x0 = bx * 16, y0 = by * 16;
    const int cbase = q * (CB / CQ);
    const float* inb = in + (size_t)b * CB * HW;

    for (int c0 = cbase; c0 < cbase + CB / CQ; c0 += 8) {
        for (int e = tid; e < 8 * 18 * 18; e += 256) {
            int c = e / 324;
            int r = (e / 18) % 18;
            int col = e % 18;
            int y = y0 + r - 1, x = x0 + col - 1;
            float v = 0.f;
            if (y >= 0 && y < H_ && x >= 0 && x < W_)
                v = inb[(size_t)(c0 + c) * HW + y * W_ + x];
            s_in[c][r][col] = v;
        }
        for (int e = tid; e < 8 * 9 * 28; e += 256) {
            int c = e / (9 * 28);
            int k = (e / 28) % 9;
            int j = e % 28;
            s_w[c][k][j] = (j < 27) ? w[((size_t)j * CB + c0 + c) * 9 + k] : 0.f;
        }
        __syncthreads();
#pragma unroll
        for (int c = 0; c < 8; c++) {
#pragma unroll
            for (int k = 0; k < 9; k++) {
                const float v = s_in[c][ty + k / 3][tx + k % 3];
                const float4* wr = (const float4*)&s_w[c][k][0];
#pragma unroll
                for (int qq = 0; qq < 7; qq++) {
                    const float4 w4 = wr[qq];
                    acc[qq * 4 + 0] += v * w4.x;
                    acc[qq * 4 + 1] += v * w4.y;
                    acc[qq * 4 + 2] += v * w4.z;
                    acc[qq * 4 + 3] += v * w4.w;
                }
            }
        }
        __syncthreads();
    }
    const int hw = (y0 + ty) * W_ + x0 + tx;
    float* op = omp + (size_t)q * B_ * 27 * HW + (size_t)b * 27 * HW;
#pragma unroll
    for (int j = 0; j < 27; j++)
        op[(size_t)j * HW + hw] = acc[j];
}

// ---------------- deformable bilinear sampling -----------------------------
__global__ void __launch_bounds__(256) deform_sample_kernel(
    const float* __restrict__ out1,
    const float* __restrict__ omp,
    const float* __restrict__ boff,
    float* __restrict__ sampled)
{
    const int idx = blockIdx.x * blockDim.x + threadIdx.x;
    if (idx >= DSPLIT * B_ * KOFF * HW) return;
    const int hw = idx % HW;
    const int k  = (idx / HW) % KOFF;
    const int b  = (idx / (HW * KOFF)) % B_;
    const int part = idx / (HW * KOFF * B_);
    const int h = hw / W_, w = hw % W_;

    const size_t qstride = (size_t)B_ * 27 * HW;
    const float* o0 = omp + (size_t)b * 27 * HW;
    float offx = boff[k], offy = boff[KOFF + k], mraw = boff[18 + k];
#pragma unroll
    for (int q = 0; q < CQ; q++) {
        const float* oq = o0 + q * qstride;
        offx += oq[(size_t)k * HW + hw];
        offy += oq[(size_t)(KOFF + k) * HW + hw];
        mraw += oq[(size_t)(18 + k) * HW + hw];
    }
    const float mval = 1.f / (1.f + expf(-mraw));

    const float py = (float)(h + k / 3 - 1) + offy;
    const float px = (float)(w + k % 3 - 1) + offx;
    const float y0f = floorf(py), x0f = floorf(px);
    const int y0 = (int)y0f, x0 = (int)x0f;
    const float wy1 = py - y0f, wx1 = px - x0f;
    const float wy0 = 1.f - wy1, wx0 = 1.f - wx1;
    const int y1 = y0 + 1, x1 = x0 + 1;
    const bool vy0 = (y0 >= 0) && (y0 < H_), vy1 = (y1 >= 0) && (y1 < H_);
    const bool vx0 = (x0 >= 0) && (x0 < W_), vx1 = (x1 >= 0) && (x1 < W_);
    const int cy0 = min(max(y0, 0), H_ - 1), cy1 = min(max(y1, 0), H_ - 1);
    const int cx0 = min(max(x0, 0), W_ - 1), cx1 = min(max(x1, 0), W_ - 1);
    const int i00 = cy0 * W_ + cx0, i01 = cy0 * W_ + cx1;
    const int i10 = cy1 * W_ + cx0, i11 = cy1 * W_ + cx1;
    const float w00 = (vy0 && vx0) ? wy0 * wx0 * mval : 0.f;
    const float w01 = (vy0 && vx1) ? wy0 * wx1 * mval : 0.f;
    const float w10 = (vy1 && vx0) ? wy1 * wx0 * mval : 0.f;
    const float w11 = (vy1 && vx1) ? wy1 * wx1 * mval : 0.f;

    const int c0 = part * (CB / DSPLIT);
    const float* base = out1 + (size_t)b * CB * HW;
    const size_t obase = (size_t)b * CB * KOFF * HW + (size_t)k * HW + hw;
#pragma unroll 8
    for (int c = c0; c < c0 + CB / DSPLIT; c++) {
        const float* p = base + (size_t)c * HW;
        float v = w00 * p[i00] + w01 * p[i01] + w10 * p[i10] + w11 * p[i11];
        sampled[obase + (size_t)c * (KOFF * HW)] = round_tf32(v);
    }
}

// ---------------- host launcher --------------------------------------------
extern "C" void kernel_launch(void* const* d_in, const int* in_sizes, int n_in,
                              void* d_out, int out_size)
{
    const float* x     = (const float*)d_in[0];
    const float* w1    = (const float*)d_in[1];
    const float* gn1s  = (const float*)d_in[2];
    const float* gn1b  = (const float*)d_in[3];
    const float* w_off = (const float*)d_in[4];
    const float* b_off = (const float*)d_in[5];
    const float* w2    = (const float*)d_in[6];
    const float* gn2s  = (const float*)d_in[7];
    const float* gn2b  = (const float*)d_in[8];
    const float* w3    = (const float*)d_in[9];
    const float* gn3s  = (const float*)d_in[10];
    const float* gn3b  = (const float*)d_in[11];
    float* out = (float*)d_out;

    float *p_out1, *p_omp, *p_samp, *p_out2, *p_out3, *p_ap1, *p_ap2, *p_ap3,
          *p_gnp, *p_gns;
    cudaGetSymbolAddress((void**)&p_out1, g_out1);
    cudaGetSymbolAddress((void**)&p_omp,  g_omp);
    cudaGetSymbolAddress((void**)&p_samp, g_samp);
    cudaGetSymbolAddress((void**)&p_out2, g_out2);
    cudaGetSymbolAddress((void**)&p_out3, g_out3);
    cudaGetSymbolAddress((void**)&p_ap1,  g_ap1);
    cudaGetSymbolAddress((void**)&p_ap2,  g_ap2);
    cudaGetSymbolAddress((void**)&p_ap3,  g_ap3);
    cudaGetSymbolAddress((void**)&p_gnp,  g_gnp);
    cudaGetSymbolAddress((void**)&p_gns,  g_gns);

    cudaFuncSetAttribute(tf32_gemm_kernel,
                         cudaFuncAttributeMaxDynamicSharedMemorySize, GEMM_SMEM);

    // launch order keeps gemm1 at captured index 3 (0-based)
    aperm_round_kernel<<<(CB*CIN + 255)/256, 256>>>(w1, p_ap1, CB, CIN);
    aperm_round_kernel<<<(CB*CB*KOFF + 255)/256, 256>>>(w2, p_ap2, CB, CB*KOFF);
    aperm_round_kernel<<<(CIN*CB + 255)/256, 256>>>(w3, p_ap3, CIN, CB);

    // 1) out1 = w1 @ x  + GN1 tile stats (8-row groups)
    tf32_gemm_kernel<<<dim3(HW/128, CB/128, B_), 256, GEMM_SMEM>>>(
        p_ap1, x, p_out1, CB, HW, CIN, (size_t)CIN*HW, (size_t)CB*HW, p_gnp, 1);

    // 1b) reduce + 2) GN1 apply + ReLU (flat, in place)
    gn_reduce_kernel<<<1, 128>>>(p_gnp, p_gns, 8.f * HW);
    gn_apply_relu_kernel<CB, 8><<<(B_*CB*HW/4 + 255)/256, 256>>>(
        p_out1, p_gns, gn1s, gn1b);

    // 3) offset conv, channel-split 8 -> partials
    conv_off_kernel<<<dim3(W_/16, H_/16, B_*CQ), 256>>>(p_out1, w_off, p_omp);

    // 4) deform sample * sigmoid(mask) -> rounded [b][c*9+k][hw]
    deform_sample_kernel<<<(DSPLIT*B_*KOFF*HW + 255)/256, 256>>>(
        p_out1, p_omp, b_off, p_samp);

    // 5) out2 = w2 @ sampled  + GN2 tile stats
    tf32_gemm_kernel<<<dim3(HW/128, CB/128, B_), 256, GEMM_SMEM>>>(
        p_ap2, p_samp, p_out2, CB, HW, CB*KOFF,
        (size_t)CB*KOFF*HW, (size_t)CB*HW, p_gnp, 1);

    // 5b) reduce + 6) GN2 apply + ReLU (flat; GEMM3 hw-truncates B)
    gn_reduce_kernel<<<1, 128>>>(p_gnp, p_gns, 8.f * HW);
    gn_apply_relu_kernel<CB, 8><<<(B_*CB*HW/4 + 255)/256, 256>>>(
        p_out2, p_gns, gn2s, gn2b);

    // 7) out3 = w3 @ out2  + GN3 tile stats (32-row groups)
    tf32_gemm_kernel<<<dim3(HW/128, CIN/128, B_), 256, GEMM_SMEM>>>(
        p_ap3, p_out2, p_out3, CIN, HW, CB, (size_t)CB*HW, (size_t)CIN*HW, p_gnp, 2);

    // 7b) reduce + 8) out = relu(GN3(out3) + x)
    gn_reduce_kernel<<<1, 128>>>(p_gnp, p_gns, 32.f * HW);
    gn_res_apply_kernel<<<(B_*CIN*HW/4 + 255)/256, 256>>>(
        p_out3, x, p_gns, gn3s, gn3b, out);
}